// round 13
// baseline (speedup 1.0000x reference)
#include <cuda_runtime.h>
#include <cuda_fp16.h>
#include <cstdint>

// Problem constants (fixed by the reference config)
#define SEQ   512
#define BATCH 64
#define NN    1024
#define SIN   64
#define NT    256          // lif threads per block (4 neurons / thread)
#define NWARP (NT/32)      // 8
#define ROW2  (NN/4)       // 256 uint2 (4 halves each) per weight/I1 row
#define ZOFF2 (NN*(NN/4))  // uint2 offset of the implicit zero row (bss-zeroed)

// Precompute kernel geometry
#define SLICES   16        // 16 column slices of 64 neurons each
#define CHUNKS   32        // tb chunks; grid = SLICES*CHUNKS = 512
#define TBC      (SEQ*BATCH/CHUNKS)   // 1024 tb per CTA
#define SLICE_U2 16        // uint2 per row in a slice (64 cols)
#define WSTRIDE  17        // padded row stride in uint2 (bank spread)
#define ZROW     (1024*WSTRIDE)
// dynamic smem carve (bytes)
#define SW_BYTES   (1025*WSTRIDE*8)          // 139400
#define OFF_BASE   139408                    // 16-aligned
#define OFF_BYTES  (2*16*64*4)               // 8192
#define NP_BASE    (OFF_BASE + OFF_BYTES)    // 147600
#define PRE_SMEM   (NP_BASE + 128)           // 147728

// Transposed fp16 weights + one trailing zero row each (zero-initialized bss).
__device__ __align__(16) __half g_W1H[NN * NN + NN];
__device__ __align__(16) __half g_W2H[NN * NN + NN];
// Precomputed layer-1 input currents I1[t][b][n], fp16.
__device__ __align__(16) __half g_I1[(size_t)SEQ * BATCH * NN];

// ---------------------------------------------------------------------------
// Tiled transpose+convert of both 1024x1024 fp32 matrices to fp16.
// ---------------------------------------------------------------------------
__global__ void transpose_both(const float* __restrict__ W1in,
                               const float* __restrict__ W2in) {
    __shared__ float tile[32][33];
    const float* in  = blockIdx.z ? W2in : W1in;
    __half*      out = blockIdx.z ? g_W2H : g_W1H;
    int bx = blockIdx.x * 32, by = blockIdx.y * 32;
    int tx = threadIdx.x, ty = threadIdx.y;
#pragma unroll
    for (int j = 0; j < 32; j += 8)
        tile[ty + j][tx] = in[(size_t)(by + ty + j) * NN + (bx + tx)];
    __syncthreads();
#pragma unroll
    for (int j = 0; j < 32; j += 8)
        out[(size_t)(bx + ty + j) * NN + (by + tx)] = __float2half(tile[tx][ty + j]);
}

// ---------------------------------------------------------------------------
// Prefill the fast-path outputs: ids tensors = iota(64), count tensors = 0.
// The sequential kernel's no-spike fast path then writes only state traces;
// its slow path overwrites these with exact values when spikes occur.
// ---------------------------------------------------------------------------
#define IDS_ELEMS ((size_t)SEQ * BATCH * SIN)
#define CNT_ELEMS ((size_t)SEQ * BATCH * 2)
__global__ void prefill_outputs(float* __restrict__ out) {
    size_t i = (size_t)blockIdx.x * 256 + threadIdx.x;   // float4 index
    size_t base = i * 4;
    if (base < 2 * IDS_ELEMS) {
        float4 v = make_float4((float)((base + 0) & 63), (float)((base + 1) & 63),
                               (float)((base + 2) & 63), (float)((base + 3) & 63));
        ((float4*)out)[i] = v;
    } else if (base < 2 * IDS_ELEMS + 2 * CNT_ELEMS) {
        ((float4*)out)[i] = make_float4(0.f, 0.f, 0.f, 0.f);
    }
}

// ---------------------------------------------------------------------------
// Precompute I1 with the W1 slice resident in shared memory. One CTA owns a
// 64-column slice of W1 (staged once, padded stride vs bank conflicts, plus a
// zero row for padding) and gathers 1024 (t,b) rows from smem, fp32 accum.
// L2 traffic: slice loads + ids only (~0.3 GB vs 2.1 GB for gmem gathers).
// ---------------------------------------------------------------------------
__global__ __launch_bounds__(NT)
void precompute_I1(const int* __restrict__ spk_ids, const int* __restrict__ spk_num) {
    extern __shared__ char smem[];
    uint2* sW    = (uint2*)smem;                          // [1025*17]
    int  (*s_off)[16][64] = (int (*)[16][64])(smem + OFF_BASE);
    int  (*s_np)[16]      = (int (*)[16])(smem + NP_BASE);

    const int tid    = threadIdx.x;
    const int slice  = blockIdx.x >> 5;        // 0..15
    const int chunk  = blockIdx.x & 31;        // 0..31
    const int tb0    = chunk * TBC;

    // ---- stage W1 slice into smem (rows 0..1023, 16 uint2 each) ----
    const uint2* W1u = (const uint2*)g_W1H;
    for (int i = tid; i < 1024 * SLICE_U2; i += NT) {
        int r = i >> 4, c = i & 15;
        sW[r * WSTRIDE + c] = W1u[(size_t)r * ROW2 + slice * SLICE_U2 + c];
    }
    if (tid < SLICE_U2) sW[ZROW + tid] = make_uint2(0u, 0u);

    const int tbL = tid >> 4;                  // 0..15: tb within group
    const int c   = tid & 15;                  // uint2 column within slice

    for (int g = 0; g < TBC / 16; g++) {
        const int buf    = g & 1;
        const int tbBase = tb0 + g * 16;

        // ---- stage padded, pre-scaled id offsets for 16 tb ----
#pragma unroll
        for (int k = 0; k < 4; k++) {
            int idx = tid + k * NT;            // 0..1023
            int tl = idx >> 6, sI = idx & 63;
            int num = __ldg(spk_num + tbBase + tl);
            int raw = __ldg(spk_ids + (size_t)(tbBase + tl) * SIN + sI);
            s_off[buf][tl][sI] = (sI < num) ? raw * WSTRIDE : ZROW;
        }
        if (tid < 16) s_np[buf][tid] = (__ldg(spk_num + tbBase + tid) + 7) & ~7;
        __syncthreads();   // sW ready (first iter) + s_off[buf] ready

        // ---- gather-accumulate from smem ----
        float4 pa = make_float4(0.f, 0.f, 0.f, 0.f), pb = pa;
        const int np = s_np[buf][tbL];
        const int* offs = s_off[buf][tbL];
        for (int s = 0; s < np; s += 8) {
            int4 oa = *(const int4*)(offs + s);
            int4 ob = *(const int4*)(offs + s + 4);
            uint2 w0 = sW[oa.x + c], w1 = sW[oa.y + c],
                  w2 = sW[oa.z + c], w3 = sW[oa.w + c];
            uint2 w4 = sW[ob.x + c], w5 = sW[ob.y + c],
                  w6 = sW[ob.z + c], w7 = sW[ob.w + c];
            float2 a, b;
            a = __half22float2(*(__half2*)&w0.x); b = __half22float2(*(__half2*)&w0.y);
            pa.x += a.x; pa.y += a.y; pa.z += b.x; pa.w += b.y;
            a = __half22float2(*(__half2*)&w1.x); b = __half22float2(*(__half2*)&w1.y);
            pb.x += a.x; pb.y += a.y; pb.z += b.x; pb.w += b.y;
            a = __half22float2(*(__half2*)&w2.x); b = __half22float2(*(__half2*)&w2.y);
            pa.x += a.x; pa.y += a.y; pa.z += b.x; pa.w += b.y;
            a = __half22float2(*(__half2*)&w3.x); b = __half22float2(*(__half2*)&w3.y);
            pb.x += a.x; pb.y += a.y; pb.z += b.x; pb.w += b.y;
            a = __half22float2(*(__half2*)&w4.x); b = __half22float2(*(__half2*)&w4.y);
            pa.x += a.x; pa.y += a.y; pa.z += b.x; pa.w += b.y;
            a = __half22float2(*(__half2*)&w5.x); b = __half22float2(*(__half2*)&w5.y);
            pb.x += a.x; pb.y += a.y; pb.z += b.x; pb.w += b.y;
            a = __half22float2(*(__half2*)&w6.x); b = __half22float2(*(__half2*)&w6.y);
            pa.x += a.x; pa.y += a.y; pa.z += b.x; pa.w += b.y;
            a = __half22float2(*(__half2*)&w7.x); b = __half22float2(*(__half2*)&w7.y);
            pb.x += a.x; pb.y += a.y; pb.z += b.x; pb.w += b.y;
        }
        float4 acc = make_float4(pa.x + pb.x, pa.y + pb.y, pa.z + pb.z, pa.w + pb.w);

        // ---- store 4 fp16 currents ----
        __half2 h01 = __floats2half2_rn(acc.x, acc.y);
        __half2 h23 = __floats2half2_rn(acc.z, acc.w);
        uint2 o;
        o.x = *reinterpret_cast<unsigned*>(&h01);
        o.y = *reinterpret_cast<unsigned*>(&h23);
        ((uint2*)g_I1)[(size_t)(tbBase + tbL) * ROW2 + slice * SLICE_U2 + c] = o;
    }
}

// ---------------------------------------------------------------------------
// Gather-accumulate fp16 rows from gmem (layer-2 slow path only).
// ---------------------------------------------------------------------------
__device__ __forceinline__ float4 gather_h2(const uint2* __restrict__ W,
                                            const int* __restrict__ off,
                                            int numPad, int tid)
{
    float4 acc = make_float4(0.f, 0.f, 0.f, 0.f);
    for (int cc = 0; cc < numPad; cc += 16) {
        uint2 w[16];
#pragma unroll
        for (int j = 0; j < 16; j++)
            w[j] = W[off[cc + j] + tid];
        float4 p0 = make_float4(0.f,0.f,0.f,0.f), p1 = p0, p2 = p0, p3 = p0;
#pragma unroll
        for (int j = 0; j < 16; j += 4) {
            float2 a0 = __half22float2(*reinterpret_cast<__half2*>(&w[j+0].x));
            float2 b0 = __half22float2(*reinterpret_cast<__half2*>(&w[j+0].y));
            p0.x += a0.x; p0.y += a0.y; p0.z += b0.x; p0.w += b0.y;
            float2 a1 = __half22float2(*reinterpret_cast<__half2*>(&w[j+1].x));
            float2 b1 = __half22float2(*reinterpret_cast<__half2*>(&w[j+1].y));
            p1.x += a1.x; p1.y += a1.y; p1.z += b1.x; p1.w += b1.y;
            float2 a2 = __half22float2(*reinterpret_cast<__half2*>(&w[j+2].x));
            float2 b2 = __half22float2(*reinterpret_cast<__half2*>(&w[j+2].y));
            p2.x += a2.x; p2.y += a2.y; p2.z += b2.x; p2.w += b2.y;
            float2 a3 = __half22float2(*reinterpret_cast<__half2*>(&w[j+3].x));
            float2 b3 = __half22float2(*reinterpret_cast<__half2*>(&w[j+3].y));
            p3.x += a3.x; p3.y += a3.y; p3.z += b3.x; p3.w += b3.y;
        }
        acc.x += (p0.x + p1.x) + (p2.x + p3.x);
        acc.y += (p0.y + p1.y) + (p2.y + p3.y);
        acc.z += (p0.z + p1.z) + (p2.z + p3.z);
        acc.w += (p0.w + p1.w) + (p2.w + p3.w);
    }
    return acc;
}

// ---------------------------------------------------------------------------
// Persistent LIF kernel. Speculative fast path: update both layers assuming
// no crossings, verify with a single __syncthreads_or per step; on the (rare)
// nonzero case restore state and replay the exact compaction logic.
// ids/cnt outputs are prefilled; fast path writes only the state traces.
// ---------------------------------------------------------------------------
__global__ __launch_bounds__(NT, 1)
void lif_persistent(const float* __restrict__ decay1, const float* __restrict__ decay2,
                    const float* __restrict__ th1,    const float* __restrict__ th2,
                    const float* __restrict__ v1init, const float* __restrict__ v2init,
                    float* __restrict__ out)
{
    const int b    = blockIdx.x;
    const int tid  = threadIdx.x;
    const int lane = tid & 31;
    const int warp = tid >> 5;

    float* out_ids1 = out;
    float* out_ids2 = out + IDS_ELEMS;
    float* out_cnt1 = out + 2 * IDS_ELEMS;
    float* out_cnt2 = out_cnt1 + CNT_ELEMS;
    float* out_st1  = out_cnt2 + CNT_ELEMS;
    float* out_st2  = out_st1 + (size_t)SEQ * BATCH * NN;

    float4 v1 = ((const float4*)v1init)[b * (NN/4) + tid];
    float4 v2 = ((const float4*)v2init)[b * (NN/4) + tid];
    const float4 d1 = ((const float4*)decay1)[tid];
    const float4 d2 = ((const float4*)decay2)[tid];
    const float4 t1 = ((const float4*)th1)[tid];
    const float4 t2 = ((const float4*)th2)[tid];
    const float4 od1 = make_float4(1.f - d1.x, 1.f - d1.y, 1.f - d1.z, 1.f - d1.w);
    const float4 od2 = make_float4(1.f - d2.x, 1.f - d2.y, 1.f - d2.z, 1.f - d2.w);
    const float4 h1 = make_float4(0.9f*t1.x, 0.9f*t1.y, 0.9f*t1.z, 0.9f*t1.w);
    const float4 h2 = make_float4(0.9f*t2.x, 0.9f*t2.y, 0.9f*t2.z, 0.9f*t2.w);

    __shared__ int s_spk[NN];
    __shared__ int s_spkoff[NN + 16];
    __shared__ int s_ns[SIN];
    __shared__ int s_spk2[SIN];
    __shared__ int s_ns2[SIN];
    __shared__ int s_wsum[NWARP];
    __shared__ int s_tot;

    const uint2* __restrict__ I1 = (const uint2*)g_I1;
    const uint2* __restrict__ W2 = (const uint2*)g_W2H;

    uint2 cur = I1[(size_t)b * ROW2 + tid];

    for (int t = 0; t < SEQ; t++) {
        int tn = (t + 1 < SEQ) ? t + 1 : t;
        uint2 nxt = I1[((size_t)tn * BATCH + b) * ROW2 + tid];
        const size_t tbIdx = (size_t)t * BATCH + b;

        // ---- speculative update of BOTH layers (assume no crossings) ----
        const float4 v1old = v1, v2old = v2;
        float2 a01 = __half22float2(*reinterpret_cast<__half2*>(&cur.x));
        float2 a23 = __half22float2(*reinterpret_cast<__half2*>(&cur.y));
        v1.x = d1.x * v1.x + od1.x * a01.x;
        v1.y = d1.y * v1.y + od1.y * a01.y;
        v1.z = d1.z * v1.z + od1.z * a23.x;
        v1.w = d1.w * v1.w + od1.w * a23.y;
        int pk1 = (int)(v1.x > t1.x) + (int)(v1.y > t1.y)
                + (int)(v1.z > t1.z) + (int)(v1.w > t1.w)
                + (((int)(v1.x > h1.x) + (int)(v1.y > h1.y)
                  + (int)(v1.z > h1.z) + (int)(v1.w > h1.w)) << 16);
        v2.x = d2.x * v2.x;     // acc2 == 0 speculation
        v2.y = d2.y * v2.y;
        v2.z = d2.z * v2.z;
        v2.w = d2.w * v2.w;
        int pk2 = (int)(v2.x > t2.x) + (int)(v2.y > t2.y)
                + (int)(v2.z > t2.z) + (int)(v2.w > t2.w)
                + (((int)(v2.x > h2.x) + (int)(v2.y > h2.y)
                  + (int)(v2.z > h2.z) + (int)(v2.w > h2.w)) << 16);

        if (__syncthreads_or(pk1 | pk2) == 0) {
            // ---- fast path: only the state traces need storing ----
            __stcs(&((float4*)out_st1)[tbIdx * (NN/4) + tid], v1);
            __stcs(&((float4*)out_st2)[tbIdx * (NN/4) + tid], v2);
        } else {
            // ---- exact replay from saved state ----
            v1 = v1old; v2 = v2old;

            // layer 1
            v1.x = d1.x * v1.x + od1.x * a01.x;
            v1.y = d1.y * v1.y + od1.y * a01.y;
            v1.z = d1.z * v1.z + od1.z * a23.x;
            v1.w = d1.w * v1.w + od1.w * a23.y;
            const bool p0 = v1.x > t1.x, p1 = v1.y > t1.y,
                       p2 = v1.z > t1.z, p3 = v1.w > t1.w;
            int c  = (int)p0 + (int)p1 + (int)p2 + (int)p3;
            int c2 = (int)(v1.x > h1.x) + (int)(v1.y > h1.y)
                   + (int)(v1.z > h1.z) + (int)(v1.w > h1.w);
            int packed = c | (c2 << 16);
            int incl = packed;
#pragma unroll
            for (int o = 1; o < 32; o <<= 1) {
                int y = __shfl_up_sync(0xffffffffu, incl, o);
                if (lane >= o) incl += y;
            }
            if (lane == 31) s_wsum[warp] = incl;
            __syncthreads();
            if (warp == 0) {
                int v = (lane < NWARP) ? s_wsum[lane] : 0;
                int e = v;
#pragma unroll
                for (int o = 1; o < NWARP; o <<= 1) {
                    int y = __shfl_up_sync(0xffffffffu, e, o);
                    if (lane >= o) e += y;
                }
                if (lane < NWARP) s_wsum[lane] = e - v;
                if (lane == NWARP - 1) s_tot = e;
            }
            __syncthreads();
            int gp          = (s_wsum[warp] + (incl - packed)) & 0xffff;
            const int c1tot = s_tot & 0xffff;
            const int c2tot = s_tot >> 16;

            const int n0 = tid * 4;
            const bool pr[4] = {p0, p1, p2, p3};
#pragma unroll
            for (int k = 0; k < 4; k++) {
                int id = n0 + k;
                if (pr[k]) { s_spk[gp] = id; s_spkoff[gp] = id * ROW2; gp++; }
                else       { int np = id - gp; if (np < SIN) s_ns[np] = id; }
            }
            if (tid < 16) s_spkoff[c1tot + tid] = ZOFF2;
            if (p0) v1.x = 0.0f;
            if (p1) v1.y = 0.0f;
            if (p2) v1.z = 0.0f;
            if (p3) v1.w = 0.0f;
            __stcs(&((float4*)out_st1)[tbIdx * (NN/4) + tid], v1);
            __syncthreads();

            if (tid < SIN) {
                int id = (tid < c1tot) ? s_spk[tid] : s_ns[tid - c1tot];
                out_ids1[tbIdx * SIN + tid] = (float)id;
            }
            if (tid < 2)
                out_cnt1[tbIdx * 2 + tid] = (float)(tid == 0 ? c1tot : c2tot);

            // layer 2
            float4 acc2 = gather_h2(W2, s_spkoff, (c1tot + 15) & ~15, tid);
            v2.x = d2.x * v2.x + od2.x * acc2.x;
            v2.y = d2.y * v2.y + od2.y * acc2.y;
            v2.z = d2.z * v2.z + od2.z * acc2.z;
            v2.w = d2.w * v2.w + od2.w * acc2.w;
            const bool q0 = v2.x > t2.x, q1 = v2.y > t2.y,
                       q2 = v2.z > t2.z, q3 = v2.w > t2.w;
            c  = (int)q0 + (int)q1 + (int)q2 + (int)q3;
            c2 = (int)(v2.x > h2.x) + (int)(v2.y > h2.y)
               + (int)(v2.z > h2.z) + (int)(v2.w > h2.w);
            packed = c | (c2 << 16);
            incl = packed;
#pragma unroll
            for (int o = 1; o < 32; o <<= 1) {
                int y = __shfl_up_sync(0xffffffffu, incl, o);
                if (lane >= o) incl += y;
            }
            if (lane == 31) s_wsum[warp] = incl;
            __syncthreads();
            if (warp == 0) {
                int v = (lane < NWARP) ? s_wsum[lane] : 0;
                int e = v;
#pragma unroll
                for (int o = 1; o < NWARP; o <<= 1) {
                    int y = __shfl_up_sync(0xffffffffu, e, o);
                    if (lane >= o) e += y;
                }
                if (lane < NWARP) s_wsum[lane] = e - v;
                if (lane == NWARP - 1) s_tot = e;
            }
            __syncthreads();
            int gq           = (s_wsum[warp] + (incl - packed)) & 0xffff;
            const int c1tot2 = s_tot & 0xffff;
            const int c2tot2 = s_tot >> 16;

            const bool qr[4] = {q0, q1, q2, q3};
#pragma unroll
            for (int k = 0; k < 4; k++) {
                int id = n0 + k;
                if (qr[k]) { if (gq < SIN) s_spk2[gq] = id; gq++; }
                else       { int np = id - gq; if (np < SIN) s_ns2[np] = id; }
            }
            if (q0) v2.x = 0.0f;
            if (q1) v2.y = 0.0f;
            if (q2) v2.z = 0.0f;
            if (q3) v2.w = 0.0f;
            __stcs(&((float4*)out_st2)[tbIdx * (NN/4) + tid], v2);
            __syncthreads();

            if (tid < SIN) {
                int id = (tid < c1tot2) ? s_spk2[tid] : s_ns2[tid - c1tot2];
                out_ids2[tbIdx * SIN + tid] = (float)id;
            }
            if (tid < 2)
                out_cnt2[tbIdx * 2 + tid] = (float)(tid == 0 ? c1tot2 : c2tot2);
        }

        cur = nxt;
    }
}

// ---------------------------------------------------------------------------
extern "C" void kernel_launch(void* const* d_in, const int* in_sizes, int n_in,
                              void* d_out, int out_size) {
    const float* W1     = (const float*)d_in[0];
    const float* W2     = (const float*)d_in[1];
    const float* decay1 = (const float*)d_in[2];
    const float* decay2 = (const float*)d_in[3];
    const float* th1    = (const float*)d_in[4];
    const float* th2    = (const float*)d_in[5];
    const float* v1init = (const float*)d_in[6];
    const float* v2init = (const float*)d_in[7];
    const int*   spkids = (const int*)d_in[8];
    const int*   spknum = (const int*)d_in[9];
    float* out = (float*)d_out;

    // opt-in smem for the sliced precompute (idempotent; first call is outside
    // graph capture, so the attribute is set before the captured launch too)
    cudaFuncSetAttribute(precompute_I1,
                         cudaFuncAttributeMaxDynamicSharedMemorySize, PRE_SMEM);

    prefill_outputs<<<4224, 256>>>(out);
    dim3 tb(32, 8), tg(32, 32, 2);
    transpose_both<<<tg, tb>>>(W1, W2);
    precompute_I1<<<SLICES * CHUNKS, NT, PRE_SMEM>>>(spkids, spknum);
    lif_persistent<<<BATCH, NT>>>(decay1, decay2, th1, th2,
                                  v1init, v2init, out);
}

// round 14
// speedup vs baseline: 1.5200x; 1.5200x over previous
#include <cuda_runtime.h>
#include <cuda_fp16.h>
#include <cstdint>

// Problem constants (fixed by the reference config)
#define SEQ   512
#define BATCH 64
#define NN    1024
#define SIN   64
#define NWARP 8
#define ROW2  (NN/4)       // 256 uint2 (4 halves each) per weight row
#define ZOFF2 (NN*(NN/4))  // uint2 offset of the implicit zero row (bss-zeroed)
#define IDS_ELEMS ((size_t)SEQ * BATCH * SIN)
#define CNT_ELEMS ((size_t)SEQ * BATCH * 2)

// Transposed fp16 weights + one trailing zero row each (zero-initialized bss).
__device__ __align__(16) __half g_W1H[NN * NN + NN];
__device__ __align__(16) __half g_W2H[NN * NN + NN];
// Per-batch "crossing happened" flags; cleared by prefill, set by phase A,
// consumed by the fixup kernel. Deterministic across graph replays.
__device__ unsigned g_flags[BATCH];

// ---------------------------------------------------------------------------
// Tiled transpose+convert of both 1024x1024 fp32 matrices to fp16.
// ---------------------------------------------------------------------------
__global__ void transpose_both(const float* __restrict__ W1in,
                               const float* __restrict__ W2in) {
    __shared__ float tile[32][33];
    const float* in  = blockIdx.z ? W2in : W1in;
    __half*      out = blockIdx.z ? g_W2H : g_W1H;
    int bx = blockIdx.x * 32, by = blockIdx.y * 32;
    int tx = threadIdx.x, ty = threadIdx.y;
#pragma unroll
    for (int j = 0; j < 32; j += 8)
        tile[ty + j][tx] = in[(size_t)(by + ty + j) * NN + (bx + tx)];
    __syncthreads();
#pragma unroll
    for (int j = 0; j < 32; j += 8)
        out[(size_t)(bx + ty + j) * NN + (by + tx)] = __float2half(tile[tx][ty + j]);
}

// ---------------------------------------------------------------------------
// Prefill fast-path outputs (ids = iota(64), cnt = 0) and clear flags.
// ---------------------------------------------------------------------------
__global__ void prefill_outputs(float* __restrict__ out) {
    if (blockIdx.x == 0 && threadIdx.x < BATCH) g_flags[threadIdx.x] = 0u;
    size_t i = (size_t)blockIdx.x * 256 + threadIdx.x;   // float4 index
    size_t base = i * 4;
    if (base < 2 * IDS_ELEMS) {
        float4 v = make_float4((float)((base + 0) & 63), (float)((base + 1) & 63),
                               (float)((base + 2) & 63), (float)((base + 3) & 63));
        ((float4*)out)[i] = v;
    } else if (base < 2 * IDS_ELEMS + 2 * CNT_ELEMS) {
        ((float4*)out)[i] = make_float4(0.f, 0.f, 0.f, 0.f);
    }
}

// ---------------------------------------------------------------------------
// Phase A: fully decoupled per-neuron LIF assuming no threshold crossings.
// One CTA = (batch b, slice of 256 neurons). 4 spike-groups of 64 threads
// gather the (t,b) spike rows' 512B W1 slice directly from L2 (16
// unconditional LDG.64 per thread; padded ids hit the L1-resident zero row).
// Group 0 owns v1, group 1 owns v2 (pure decay — layer-2 input is zero unless
// layer 1 spikes, which sets the flag). One barrier per step.
// Any crossing of th or 0.9*th in either layer sets g_flags[b]; the fixup
// kernel then recomputes that batch exactly.
// ---------------------------------------------------------------------------
__global__ __launch_bounds__(256, 2)
void lif_phaseA(const float* __restrict__ decay1, const float* __restrict__ decay2,
                const float* __restrict__ th1,    const float* __restrict__ th2,
                const float* __restrict__ v1init, const float* __restrict__ v2init,
                const int* __restrict__ spk_ids,  const int* __restrict__ spk_num,
                float* __restrict__ out)
{
    const int b     = blockIdx.x >> 2;
    const int slice = blockIdx.x & 3;
    const int tid   = threadIdx.x;
    const int g     = tid >> 6;        // spike group 0..3 (2 warps each)
    const int col   = tid & 63;        // uint2 column within the 256-neuron slice
    const int cix   = slice * 64 + col;  // uint2 index within a row; float4 idx in NN

    float* out_st1 = out + 2 * IDS_ELEMS + 2 * CNT_ELEMS;
    float* out_st2 = out_st1 + (size_t)SEQ * BATCH * NN;

    __shared__ int    s_off[2][SIN];       // double-buffered pre-scaled row offsets
    __shared__ float4 s_part[2][3][64];    // partial sums from groups 1..3

    // Per-group state (uniform branches: groups are whole warps)
    float4 v1, d1, od1, h1, t1;
    float4 v2, d2, h2, t2v;
    if (g == 0) {
        v1 = ((const float4*)v1init)[b * (NN/4) + cix];
        d1 = ((const float4*)decay1)[cix];
        t1 = ((const float4*)th1)[cix];
        od1 = make_float4(1.f - d1.x, 1.f - d1.y, 1.f - d1.z, 1.f - d1.w);
        h1 = make_float4(0.9f*t1.x, 0.9f*t1.y, 0.9f*t1.z, 0.9f*t1.w);
    } else if (g == 1) {
        v2 = ((const float4*)v2init)[b * (NN/4) + cix];
        d2 = ((const float4*)decay2)[cix];
        t2v = ((const float4*)th2)[cix];
        h2 = make_float4(0.9f*t2v.x, 0.9f*t2v.y, 0.9f*t2v.z, 0.9f*t2v.w);
    }

    // Stage step-0 ids (padded with zero-row offsets)
    if (tid < SIN) {
        int num = spk_num[b];
        int id  = spk_ids[(size_t)b * SIN + tid];
        s_off[0][tid] = (tid < num) ? id * ROW2 : ZOFF2;
    }
    __syncthreads();

    const uint2* __restrict__ W1u = (const uint2*)g_W1H;
    unsigned flag = 0;

    for (int t = 0; t < SEQ; t++) {
        const int buf = t & 1;

        // group 3 prefetches step t+1 ids (latency hidden under the step)
        int nid = 0, nnum = 0;
        if (g == 3) {
            int tn = (t + 1 < SEQ) ? t + 1 : t;
            nnum = spk_num[tn * BATCH + b];
            nid  = spk_ids[((size_t)tn * BATCH + b) * SIN + col];
        }

        // ---- unconditional 16-row gather for this group (s = 4k + g) ----
        uint2 w[16];
#pragma unroll
        for (int k = 0; k < 16; k++)
            w[k] = W1u[s_off[buf][4*k + g] + cix];

        float4 p0 = make_float4(0.f,0.f,0.f,0.f), p1 = p0, p2 = p0, p3 = p0;
#pragma unroll
        for (int k = 0; k < 16; k += 4) {
            float2 a, bb;
            a = __half22float2(*(__half2*)&w[k+0].x); bb = __half22float2(*(__half2*)&w[k+0].y);
            p0.x += a.x; p0.y += a.y; p0.z += bb.x; p0.w += bb.y;
            a = __half22float2(*(__half2*)&w[k+1].x); bb = __half22float2(*(__half2*)&w[k+1].y);
            p1.x += a.x; p1.y += a.y; p1.z += bb.x; p1.w += bb.y;
            a = __half22float2(*(__half2*)&w[k+2].x); bb = __half22float2(*(__half2*)&w[k+2].y);
            p2.x += a.x; p2.y += a.y; p2.z += bb.x; p2.w += bb.y;
            a = __half22float2(*(__half2*)&w[k+3].x); bb = __half22float2(*(__half2*)&w[k+3].y);
            p3.x += a.x; p3.y += a.y; p3.z += bb.x; p3.w += bb.y;
        }
        float4 acc = make_float4((p0.x + p1.x) + (p2.x + p3.x),
                                 (p0.y + p1.y) + (p2.y + p3.y),
                                 (p0.z + p1.z) + (p2.z + p3.z),
                                 (p0.w + p1.w) + (p2.w + p3.w));

        if (g != 0) s_part[buf][g-1][col] = acc;
        if (g == 3) s_off[buf ^ 1][col] = (col < nnum) ? nid * ROW2 : ZOFF2;
        __syncthreads();    // the ONLY barrier per step

        const size_t tbIdx = (size_t)t * BATCH + b;
        if (g == 0) {
            float4 q0 = s_part[buf][0][col], q1 = s_part[buf][1][col],
                   q2 = s_part[buf][2][col];
            acc.x += (q0.x + q1.x) + q2.x;
            acc.y += (q0.y + q1.y) + q2.y;
            acc.z += (q0.z + q1.z) + q2.z;
            acc.w += (q0.w + q1.w) + q2.w;
            v1.x = d1.x * v1.x + od1.x * acc.x;
            v1.y = d1.y * v1.y + od1.y * acc.y;
            v1.z = d1.z * v1.z + od1.z * acc.z;
            v1.w = d1.w * v1.w + od1.w * acc.w;
            if (v1.x > h1.x || v1.y > h1.y || v1.z > h1.z || v1.w > h1.w ||
                v1.x > t1.x || v1.y > t1.y || v1.z > t1.z || v1.w > t1.w) flag = 1;
            __stcs(&((float4*)out_st1)[tbIdx * (NN/4) + cix], v1);
        } else if (g == 1) {
            v2.x = d2.x * v2.x;
            v2.y = d2.y * v2.y;
            v2.z = d2.z * v2.z;
            v2.w = d2.w * v2.w;
            if (v2.x > h2.x || v2.y > h2.y || v2.z > h2.z || v2.w > h2.w ||
                v2.x > t2v.x || v2.y > t2v.y || v2.z > t2v.z || v2.w > t2v.w) flag = 1;
            __stcs(&((float4*)out_st2)[tbIdx * (NN/4) + cix], v2);
        }
    }
    if (flag) atomicOr(&g_flags[b], 1u);
}

// ---------------------------------------------------------------------------
// Gather-accumulate fp16 rows from gmem (fixup path). off[] pre-scaled,
// padded to numPad (multiple of 16) with zero-row offsets.
// ---------------------------------------------------------------------------
__device__ __forceinline__ float4 gather_h2(const uint2* __restrict__ W,
                                            const int* __restrict__ off,
                                            int numPad, int tid)
{
    float4 acc = make_float4(0.f, 0.f, 0.f, 0.f);
    for (int cc = 0; cc < numPad; cc += 16) {
        uint2 w[16];
#pragma unroll
        for (int j = 0; j < 16; j++)
            w[j] = W[off[cc + j] + tid];
        float4 p0 = make_float4(0.f,0.f,0.f,0.f), p1 = p0, p2 = p0, p3 = p0;
#pragma unroll
        for (int j = 0; j < 16; j += 4) {
            float2 a0 = __half22float2(*reinterpret_cast<__half2*>(&w[j+0].x));
            float2 b0 = __half22float2(*reinterpret_cast<__half2*>(&w[j+0].y));
            p0.x += a0.x; p0.y += a0.y; p0.z += b0.x; p0.w += b0.y;
            float2 a1 = __half22float2(*reinterpret_cast<__half2*>(&w[j+1].x));
            float2 b1 = __half22float2(*reinterpret_cast<__half2*>(&w[j+1].y));
            p1.x += a1.x; p1.y += a1.y; p1.z += b1.x; p1.w += b1.y;
            float2 a2 = __half22float2(*reinterpret_cast<__half2*>(&w[j+2].x));
            float2 b2 = __half22float2(*reinterpret_cast<__half2*>(&w[j+2].y));
            p2.x += a2.x; p2.y += a2.y; p2.z += b2.x; p2.w += b2.y;
            float2 a3 = __half22float2(*reinterpret_cast<__half2*>(&w[j+3].x));
            float2 b3 = __half22float2(*reinterpret_cast<__half2*>(&w[j+3].y));
            p3.x += a3.x; p3.y += a3.y; p3.z += b3.x; p3.w += b3.y;
        }
        acc.x += (p0.x + p1.x) + (p2.x + p3.x);
        acc.y += (p0.y + p1.y) + (p2.y + p3.y);
        acc.z += (p0.z + p1.z) + (p2.z + p3.z);
        acc.w += (p0.w + p1.w) + (p2.w + p3.w);
    }
    return acc;
}

// ---------------------------------------------------------------------------
// Fixup: exact coupled recomputation of one batch element, run only when
// phase A flagged a threshold crossing for it. Overwrites ALL outputs of b.
// ---------------------------------------------------------------------------
__global__ __launch_bounds__(256, 1)
void lif_fixup(const float* __restrict__ decay1, const float* __restrict__ decay2,
               const float* __restrict__ th1,    const float* __restrict__ th2,
               const float* __restrict__ v1init, const float* __restrict__ v2init,
               const int* __restrict__ spk_ids,  const int* __restrict__ spk_num,
               float* __restrict__ out)
{
    const int b = blockIdx.x;
    if (g_flags[b] == 0) return;     // common case: nothing to fix

    const int tid  = threadIdx.x;
    const int lane = tid & 31;
    const int warp = tid >> 5;

    float* out_ids1 = out;
    float* out_ids2 = out + IDS_ELEMS;
    float* out_cnt1 = out + 2 * IDS_ELEMS;
    float* out_cnt2 = out_cnt1 + CNT_ELEMS;
    float* out_st1  = out_cnt2 + CNT_ELEMS;
    float* out_st2  = out_st1 + (size_t)SEQ * BATCH * NN;

    float4 v1 = ((const float4*)v1init)[b * (NN/4) + tid];
    float4 v2 = ((const float4*)v2init)[b * (NN/4) + tid];
    const float4 d1 = ((const float4*)decay1)[tid];
    const float4 d2 = ((const float4*)decay2)[tid];
    const float4 t1 = ((const float4*)th1)[tid];
    const float4 t2 = ((const float4*)th2)[tid];
    const float4 od1 = make_float4(1.f - d1.x, 1.f - d1.y, 1.f - d1.z, 1.f - d1.w);
    const float4 od2 = make_float4(1.f - d2.x, 1.f - d2.y, 1.f - d2.z, 1.f - d2.w);
    const float4 h1 = make_float4(0.9f*t1.x, 0.9f*t1.y, 0.9f*t1.z, 0.9f*t1.w);
    const float4 h2 = make_float4(0.9f*t2.x, 0.9f*t2.y, 0.9f*t2.z, 0.9f*t2.w);

    __shared__ int s_ids[SIN];
    __shared__ int s_num;
    __shared__ int s_spk[NN];
    __shared__ int s_spkoff[NN + 16];
    __shared__ int s_ns[SIN];
    __shared__ int s_spk2[SIN];
    __shared__ int s_ns2[SIN];
    __shared__ int s_wsum[NWARP];
    __shared__ int s_tot;

    const uint2* __restrict__ W1 = (const uint2*)g_W1H;
    const uint2* __restrict__ W2 = (const uint2*)g_W2H;

    for (int t = 0; t < SEQ; t++) {
        const size_t tbIdx = (size_t)t * BATCH + b;
        if (tid < SIN) {
            int num = spk_num[t * BATCH + b];
            int id  = spk_ids[tbIdx * SIN + tid];
            s_ids[tid] = (tid < num) ? id * ROW2 : ZOFF2;
            if (tid == 0) s_num = num;
        }
        __syncthreads();

        // layer 1
        const int num = s_num;
        float4 acc = gather_h2(W1, s_ids, (num + 15) & ~15, tid);
        v1.x = d1.x * v1.x + od1.x * acc.x;
        v1.y = d1.y * v1.y + od1.y * acc.y;
        v1.z = d1.z * v1.z + od1.z * acc.z;
        v1.w = d1.w * v1.w + od1.w * acc.w;
        const bool p0 = v1.x > t1.x, p1 = v1.y > t1.y,
                   p2 = v1.z > t1.z, p3 = v1.w > t1.w;
        int c  = (int)p0 + (int)p1 + (int)p2 + (int)p3;
        int c2 = (int)(v1.x > h1.x) + (int)(v1.y > h1.y)
               + (int)(v1.z > h1.z) + (int)(v1.w > h1.w);
        int packed = c | (c2 << 16);
        int incl = packed;
#pragma unroll
        for (int o = 1; o < 32; o <<= 1) {
            int y = __shfl_up_sync(0xffffffffu, incl, o);
            if (lane >= o) incl += y;
        }
        if (lane == 31) s_wsum[warp] = incl;
        __syncthreads();
        if (warp == 0) {
            int v = (lane < NWARP) ? s_wsum[lane] : 0;
            int e = v;
#pragma unroll
            for (int o = 1; o < NWARP; o <<= 1) {
                int y = __shfl_up_sync(0xffffffffu, e, o);
                if (lane >= o) e += y;
            }
            if (lane < NWARP) s_wsum[lane] = e - v;
            if (lane == NWARP - 1) s_tot = e;
        }
        __syncthreads();
        int gp          = (s_wsum[warp] + (incl - packed)) & 0xffff;
        const int c1tot = s_tot & 0xffff;
        const int c2tot = s_tot >> 16;

        const int n0 = tid * 4;
        const bool pr[4] = {p0, p1, p2, p3};
#pragma unroll
        for (int k = 0; k < 4; k++) {
            int id = n0 + k;
            if (pr[k]) { s_spk[gp] = id; s_spkoff[gp] = id * ROW2; gp++; }
            else       { int np = id - gp; if (np < SIN) s_ns[np] = id; }
        }
        if (tid < 16) s_spkoff[c1tot + tid] = ZOFF2;
        if (p0) v1.x = 0.0f;
        if (p1) v1.y = 0.0f;
        if (p2) v1.z = 0.0f;
        if (p3) v1.w = 0.0f;
        ((float4*)out_st1)[tbIdx * (NN/4) + tid] = v1;
        __syncthreads();

        if (tid < SIN) {
            int id = (tid < c1tot) ? s_spk[tid] : s_ns[tid - c1tot];
            out_ids1[tbIdx * SIN + tid] = (float)id;
        }
        if (tid < 2)
            out_cnt1[tbIdx * 2 + tid] = (float)(tid == 0 ? c1tot : c2tot);

        // layer 2
        float4 acc2 = gather_h2(W2, s_spkoff, (c1tot + 15) & ~15, tid);
        v2.x = d2.x * v2.x + od2.x * acc2.x;
        v2.y = d2.y * v2.y + od2.y * acc2.y;
        v2.z = d2.z * v2.z + od2.z * acc2.z;
        v2.w = d2.w * v2.w + od2.w * acc2.w;
        const bool q0 = v2.x > t2.x, q1 = v2.y > t2.y,
                   q2 = v2.z > t2.z, q3 = v2.w > t2.w;
        c  = (int)q0 + (int)q1 + (int)q2 + (int)q3;
        c2 = (int)(v2.x > h2.x) + (int)(v2.y > h2.y)
           + (int)(v2.z > h2.z) + (int)(v2.w > h2.w);
        packed = c | (c2 << 16);
        incl = packed;
#pragma unroll
        for (int o = 1; o < 32; o <<= 1) {
            int y = __shfl_up_sync(0xffffffffu, incl, o);
            if (lane >= o) incl += y;
        }
        if (lane == 31) s_wsum[warp] = incl;
        __syncthreads();
        if (warp == 0) {
            int v = (lane < NWARP) ? s_wsum[lane] : 0;
            int e = v;
#pragma unroll
            for (int o = 1; o < NWARP; o <<= 1) {
                int y = __shfl_up_sync(0xffffffffu, e, o);
                if (lane >= o) e += y;
            }
            if (lane < NWARP) s_wsum[lane] = e - v;
            if (lane == NWARP - 1) s_tot = e;
        }
        __syncthreads();
        int gq           = (s_wsum[warp] + (incl - packed)) & 0xffff;
        const int c1tot2 = s_tot & 0xffff;
        const int c2tot2 = s_tot >> 16;

        const bool qr[4] = {q0, q1, q2, q3};
#pragma unroll
        for (int k = 0; k < 4; k++) {
            int id = n0 + k;
            if (qr[k]) { if (gq < SIN) s_spk2[gq] = id; gq++; }
            else       { int np = id - gq; if (np < SIN) s_ns2[np] = id; }
        }
        if (q0) v2.x = 0.0f;
        if (q1) v2.y = 0.0f;
        if (q2) v2.z = 0.0f;
        if (q3) v2.w = 0.0f;
        ((float4*)out_st2)[tbIdx * (NN/4) + tid] = v2;
        __syncthreads();

        if (tid < SIN) {
            int id = (tid < c1tot2) ? s_spk2[tid] : s_ns2[tid - c1tot2];
            out_ids2[tbIdx * SIN + tid] = (float)id;
        }
        if (tid < 2)
            out_cnt2[tbIdx * 2 + tid] = (float)(tid == 0 ? c1tot2 : c2tot2);
        __syncthreads();   // s_ids rewrite next step
    }
}

// ---------------------------------------------------------------------------
extern "C" void kernel_launch(void* const* d_in, const int* in_sizes, int n_in,
                              void* d_out, int out_size) {
    const float* W1     = (const float*)d_in[0];
    const float* W2     = (const float*)d_in[1];
    const float* decay1 = (const float*)d_in[2];
    const float* decay2 = (const float*)d_in[3];
    const float* th1    = (const float*)d_in[4];
    const float* th2    = (const float*)d_in[5];
    const float* v1init = (const float*)d_in[6];
    const float* v2init = (const float*)d_in[7];
    const int*   spkids = (const int*)d_in[8];
    const int*   spknum = (const int*)d_in[9];
    float* out = (float*)d_out;

    prefill_outputs<<<4224, 256>>>(out);
    dim3 tb(32, 8), tg(32, 32, 2);
    transpose_both<<<tg, tb>>>(W1, W2);
    lif_phaseA<<<BATCH * 4, 256>>>(decay1, decay2, th1, th2,
                                   v1init, v2init, spkids, spknum, out);
    lif_fixup<<<BATCH, 256>>>(decay1, decay2, th1, th2,
                              v1init, v2init, spkids, spknum, out);
}

// round 16
// speedup vs baseline: 1.8169x; 1.1953x over previous
#include <cuda_runtime.h>
#include <cuda_fp16.h>
#include <cstdint>

// Problem constants (fixed by the reference config)
#define SEQ   512
#define BATCH 64
#define NN    1024
#define SIN   64
#define NWARP 8
#define ROW2  (NN/4)       // 256 uint2 (4 halves each) per weight row
#define ZOFF2 (NN*(NN/4))  // uint2 offset of the implicit zero row (bss-zeroed)
#define IDS_ELEMS ((size_t)SEQ * BATCH * SIN)
#define CNT_ELEMS ((size_t)SEQ * BATCH * 2)

// Transposed fp16 weights + one trailing zero row each (zero-initialized bss).
__device__ __align__(16) __half g_W1H[NN * NN + NN];
__device__ __align__(16) __half g_W2H[NN * NN + NN];
// Per-batch "crossing happened" flags; cleared by transpose_both, set by
// phase A, consumed by the fixup kernel. Deterministic across graph replays.
__device__ unsigned g_flags[BATCH];

// ---------------------------------------------------------------------------
// Tiled transpose+convert of both 1024x1024 fp32 matrices to fp16.
// Block (0,0,0) also clears the per-batch fixup flags.
// ---------------------------------------------------------------------------
__global__ void transpose_both(const float* __restrict__ W1in,
                               const float* __restrict__ W2in) {
    __shared__ float tile[32][33];
    const float* in  = blockIdx.z ? W2in : W1in;
    __half*      out = blockIdx.z ? g_W2H : g_W1H;
    int bx = blockIdx.x * 32, by = blockIdx.y * 32;
    int tx = threadIdx.x, ty = threadIdx.y;
    if (blockIdx.x == 0 && blockIdx.y == 0 && blockIdx.z == 0) {
        int flat = ty * 32 + tx;
        if (flat < BATCH) g_flags[flat] = 0u;
    }
#pragma unroll
    for (int j = 0; j < 32; j += 8)
        tile[ty + j][tx] = in[(size_t)(by + ty + j) * NN + (bx + tx)];
    __syncthreads();
#pragma unroll
    for (int j = 0; j < 32; j += 8)
        out[(size_t)(bx + ty + j) * NN + (by + tx)] = __float2half(tile[tx][ty + j]);
}

// ---------------------------------------------------------------------------
// Phase A: fully decoupled per-neuron LIF assuming no threshold crossings.
// One CTA = (batch b, slice of 256 neurons). Group g (64 threads) gathers the
// CONTIGUOUS row block [16g, 16g+16) of this step's spike list — only groups
// with g < ceil(num/16) do any work, so padding rows beyond the next
// 16-boundary are never touched (avg rows processed ~40 vs 64).
// Group 0 owns v1, group 1 owns v2 (pure decay), group 3 prefetches next ids,
// groups 2/3 of slice 0 also emit the closed-form ids/cnt outputs.
// One barrier per step. Any crossing sets g_flags[b] for exact fixup.
// ---------------------------------------------------------------------------
__global__ __launch_bounds__(256, 2)
void lif_phaseA(const float* __restrict__ decay1, const float* __restrict__ decay2,
                const float* __restrict__ th1,    const float* __restrict__ th2,
                const float* __restrict__ v1init, const float* __restrict__ v2init,
                const int* __restrict__ spk_ids,  const int* __restrict__ spk_num,
                float* __restrict__ out)
{
    const int b     = blockIdx.x >> 2;
    const int slice = blockIdx.x & 3;
    const int tid   = threadIdx.x;
    const int g     = tid >> 6;          // spike group 0..3 (2 warps each)
    const int col   = tid & 63;          // uint2 column within the 256-neuron slice
    const int cix   = slice * 64 + col;  // uint2 index within a row

    float* out_ids1 = out;
    float* out_ids2 = out + IDS_ELEMS;
    float* out_cnt1 = out + 2 * IDS_ELEMS;
    float* out_cnt2 = out_cnt1 + CNT_ELEMS;
    float* out_st1  = out_cnt2 + CNT_ELEMS;
    float* out_st2  = out_st1 + (size_t)SEQ * BATCH * NN;

    __shared__ int    s_off[2][SIN];     // double-buffered pre-scaled row offsets
    __shared__ int    s_num[2];
    __shared__ float4 s_part[2][3][64];  // partial sums from groups 1..3

    // Per-group state (uniform branches: groups are whole warps)
    float4 v1, d1, od1, h1, t1;
    float4 v2, d2, h2, t2v;
    if (g == 0) {
        v1 = ((const float4*)v1init)[b * (NN/4) + cix];
        d1 = ((const float4*)decay1)[cix];
        t1 = ((const float4*)th1)[cix];
        od1 = make_float4(1.f - d1.x, 1.f - d1.y, 1.f - d1.z, 1.f - d1.w);
        h1 = make_float4(0.9f*t1.x, 0.9f*t1.y, 0.9f*t1.z, 0.9f*t1.w);
    } else if (g == 1) {
        v2 = ((const float4*)v2init)[b * (NN/4) + cix];
        d2 = ((const float4*)decay2)[cix];
        t2v = ((const float4*)th2)[cix];
        h2 = make_float4(0.9f*t2v.x, 0.9f*t2v.y, 0.9f*t2v.z, 0.9f*t2v.w);
    }
    const float fcol = (float)col;       // closed-form id value

    // Stage step-0 ids (padded with zero-row offsets)
    if (tid < SIN) {
        int num = spk_num[b];
        int id  = spk_ids[(size_t)b * SIN + tid];
        s_off[0][tid] = (tid < num) ? id * ROW2 : ZOFF2;
        if (tid == 0) s_num[0] = num;
    }
    __syncthreads();

    const uint2* __restrict__ W1u = (const uint2*)g_W1H;
    unsigned flag = 0;

    for (int t = 0; t < SEQ; t++) {
        const int buf = t & 1;
        const size_t tbIdx = (size_t)t * BATCH + b;

        // group 3 prefetches step t+1 ids (latency hidden under the step)
        int nid = 0, nnum = 0;
        if (g == 3) {
            int tn = (t + 1 < SEQ) ? t + 1 : t;
            nnum = spk_num[tn * BATCH + b];
            nid  = spk_ids[((size_t)tn * BATCH + b) * SIN + col];
        }

        const int num  = s_num[buf];
        const int nact = (num + 15) >> 4;      // active groups (0..4)

        // ---- contiguous 16-row gather for active groups only ----
        float4 acc = make_float4(0.f, 0.f, 0.f, 0.f);
        if (g < nact) {
            uint2 w[16];
#pragma unroll
            for (int k = 0; k < 16; k++)
                w[k] = W1u[s_off[buf][g * 16 + k] + cix];
            float4 p0 = make_float4(0.f,0.f,0.f,0.f), p1 = p0, p2 = p0, p3 = p0;
#pragma unroll
            for (int k = 0; k < 16; k += 4) {
                float2 a, bb;
                a = __half22float2(*(__half2*)&w[k+0].x); bb = __half22float2(*(__half2*)&w[k+0].y);
                p0.x += a.x; p0.y += a.y; p0.z += bb.x; p0.w += bb.y;
                a = __half22float2(*(__half2*)&w[k+1].x); bb = __half22float2(*(__half2*)&w[k+1].y);
                p1.x += a.x; p1.y += a.y; p1.z += bb.x; p1.w += bb.y;
                a = __half22float2(*(__half2*)&w[k+2].x); bb = __half22float2(*(__half2*)&w[k+2].y);
                p2.x += a.x; p2.y += a.y; p2.z += bb.x; p2.w += bb.y;
                a = __half22float2(*(__half2*)&w[k+3].x); bb = __half22float2(*(__half2*)&w[k+3].y);
                p3.x += a.x; p3.y += a.y; p3.z += bb.x; p3.w += bb.y;
            }
            acc = make_float4((p0.x + p1.x) + (p2.x + p3.x),
                              (p0.y + p1.y) + (p2.y + p3.y),
                              (p0.z + p1.z) + (p2.z + p3.z),
                              (p0.w + p1.w) + (p2.w + p3.w));
            if (g != 0) s_part[buf][g-1][col] = acc;
        }

        // ---- closed-form ids/cnt outputs (slice 0 only; idle-group work) ----
        if (slice == 0) {
            if (g == 2) {
                __stcs(&out_ids1[tbIdx * SIN + col], fcol);
                if (col < 2) __stcs(&out_cnt1[tbIdx * 2 + col], 0.0f);
            } else if (g == 3) {
                __stcs(&out_ids2[tbIdx * SIN + col], fcol);
                if (col < 2) __stcs(&out_cnt2[tbIdx * 2 + col], 0.0f);
            }
        }

        // commit prefetched ids for step t+1
        if (g == 3) {
            s_off[buf ^ 1][col] = (col < nnum) ? nid * ROW2 : ZOFF2;
            if (col == 0) s_num[buf ^ 1] = nnum;
        }
        __syncthreads();    // the ONLY barrier per step

        if (g == 0) {
#pragma unroll
            for (int j = 0; j < 3; j++) {
                if (j + 1 < nact) {
                    float4 q = s_part[buf][j][col];
                    acc.x += q.x; acc.y += q.y; acc.z += q.z; acc.w += q.w;
                }
            }
            v1.x = d1.x * v1.x + od1.x * acc.x;
            v1.y = d1.y * v1.y + od1.y * acc.y;
            v1.z = d1.z * v1.z + od1.z * acc.z;
            v1.w = d1.w * v1.w + od1.w * acc.w;
            if (v1.x > h1.x || v1.y > h1.y || v1.z > h1.z || v1.w > h1.w ||
                v1.x > t1.x || v1.y > t1.y || v1.z > t1.z || v1.w > t1.w) flag = 1;
            __stcs(&((float4*)out_st1)[tbIdx * (NN/4) + cix], v1);
        } else if (g == 1) {
            v2.x = d2.x * v2.x;
            v2.y = d2.y * v2.y;
            v2.z = d2.z * v2.z;
            v2.w = d2.w * v2.w;
            if (v2.x > h2.x || v2.y > h2.y || v2.z > h2.z || v2.w > h2.w ||
                v2.x > t2v.x || v2.y > t2v.y || v2.z > t2v.z || v2.w > t2v.w) flag = 1;
            __stcs(&((float4*)out_st2)[tbIdx * (NN/4) + cix], v2);
        }
    }
    if (flag) atomicOr(&g_flags[b], 1u);
}

// ---------------------------------------------------------------------------
// Gather-accumulate fp16 rows from gmem (fixup path). off[] pre-scaled,
// padded to numPad (multiple of 16) with zero-row offsets.
// ---------------------------------------------------------------------------
__device__ __forceinline__ float4 gather_h2(const uint2* __restrict__ W,
                                            const int* __restrict__ off,
                                            int numPad, int tid)
{
    float4 acc = make_float4(0.f, 0.f, 0.f, 0.f);
    for (int cc = 0; cc < numPad; cc += 16) {
        uint2 w[16];
#pragma unroll
        for (int j = 0; j < 16; j++)
            w[j] = W[off[cc + j] + tid];
        float4 p0 = make_float4(0.f,0.f,0.f,0.f), p1 = p0, p2 = p0, p3 = p0;
#pragma unroll
        for (int j = 0; j < 16; j += 4) {
            float2 a0 = __half22float2(*reinterpret_cast<__half2*>(&w[j+0].x));
            float2 b0 = __half22float2(*reinterpret_cast<__half2*>(&w[j+0].y));
            p0.x += a0.x; p0.y += a0.y; p0.z += b0.x; p0.w += b0.y;
            float2 a1 = __half22float2(*reinterpret_cast<__half2*>(&w[j+1].x));
            float2 b1 = __half22float2(*reinterpret_cast<__half2*>(&w[j+1].y));
            p1.x += a1.x; p1.y += a1.y; p1.z += b1.x; p1.w += b1.y;
            float2 a2 = __half22float2(*reinterpret_cast<__half2*>(&w[j+2].x));
            float2 b2 = __half22float2(*reinterpret_cast<__half2*>(&w[j+2].y));
            p2.x += a2.x; p2.y += a2.y; p2.z += b2.x; p2.w += b2.y;
            float2 a3 = __half22float2(*reinterpret_cast<__half2*>(&w[j+3].x));
            float2 b3 = __half22float2(*reinterpret_cast<__half2*>(&w[j+3].y));
            p3.x += a3.x; p3.y += a3.y; p3.z += b3.x; p3.w += b3.y;
        }
        acc.x += (p0.x + p1.x) + (p2.x + p3.x);
        acc.y += (p0.y + p1.y) + (p2.y + p3.y);
        acc.z += (p0.z + p1.z) + (p2.z + p3.z);
        acc.w += (p0.w + p1.w) + (p2.w + p3.w);
    }
    return acc;
}

// ---------------------------------------------------------------------------
// Fixup: exact coupled recomputation of one batch element, run only when
// phase A flagged a threshold crossing for it. Overwrites ALL outputs of b.
// ---------------------------------------------------------------------------
__global__ __launch_bounds__(256, 1)
void lif_fixup(const float* __restrict__ decay1, const float* __restrict__ decay2,
               const float* __restrict__ th1,    const float* __restrict__ th2,
               const float* __restrict__ v1init, const float* __restrict__ v2init,
               const int* __restrict__ spk_ids,  const int* __restrict__ spk_num,
               float* __restrict__ out)
{
    const int b = blockIdx.x;
    if (g_flags[b] == 0) return;     // common case: nothing to fix

    const int tid  = threadIdx.x;
    const int lane = tid & 31;
    const int warp = tid >> 5;

    float* out_ids1 = out;
    float* out_ids2 = out + IDS_ELEMS;
    float* out_cnt1 = out + 2 * IDS_ELEMS;
    float* out_cnt2 = out_cnt1 + CNT_ELEMS;
    float* out_st1  = out_cnt2 + CNT_ELEMS;
    float* out_st2  = out_st1 + (size_t)SEQ * BATCH * NN;

    float4 v1 = ((const float4*)v1init)[b * (NN/4) + tid];
    float4 v2 = ((const float4*)v2init)[b * (NN/4) + tid];
    const float4 d1 = ((const float4*)decay1)[tid];
    const float4 d2 = ((const float4*)decay2)[tid];
    const float4 t1 = ((const float4*)th1)[tid];
    const float4 t2 = ((const float4*)th2)[tid];
    const float4 od1 = make_float4(1.f - d1.x, 1.f - d1.y, 1.f - d1.z, 1.f - d1.w);
    const float4 od2 = make_float4(1.f - d2.x, 1.f - d2.y, 1.f - d2.z, 1.f - d2.w);
    const float4 h1 = make_float4(0.9f*t1.x, 0.9f*t1.y, 0.9f*t1.z, 0.9f*t1.w);
    const float4 h2 = make_float4(0.9f*t2.x, 0.9f*t2.y, 0.9f*t2.z, 0.9f*t2.w);

    __shared__ int s_ids[SIN];
    __shared__ int s_num;
    __shared__ int s_spk[NN];
    __shared__ int s_spkoff[NN + 16];
    __shared__ int s_ns[SIN];
    __shared__ int s_spk2[SIN];
    __shared__ int s_ns2[SIN];
    __shared__ int s_wsum[NWARP];
    __shared__ int s_tot;

    const uint2* __restrict__ W1 = (const uint2*)g_W1H;
    const uint2* __restrict__ W2 = (const uint2*)g_W2H;

    for (int t = 0; t < SEQ; t++) {
        const size_t tbIdx = (size_t)t * BATCH + b;
        if (tid < SIN) {
            int num = spk_num[t * BATCH + b];
            int id  = spk_ids[tbIdx * SIN + tid];
            s_ids[tid] = (tid < num) ? id * ROW2 : ZOFF2;
            if (tid == 0) s_num = num;
        }
        __syncthreads();

        // layer 1
        const int num = s_num;
        float4 acc = gather_h2(W1, s_ids, (num + 15) & ~15, tid);
        v1.x = d1.x * v1.x + od1.x * acc.x;
        v1.y = d1.y * v1.y + od1.y * acc.y;
        v1.z = d1.z * v1.z + od1.z * acc.z;
        v1.w = d1.w * v1.w + od1.w * acc.w;
        const bool p0 = v1.x > t1.x, p1 = v1.y > t1.y,
                   p2 = v1.z > t1.z, p3 = v1.w > t1.w;
        int c  = (int)p0 + (int)p1 + (int)p2 + (int)p3;
        int c2 = (int)(v1.x > h1.x) + (int)(v1.y > h1.y)
               + (int)(v1.z > h1.z) + (int)(v1.w > h1.w);
        int packed = c | (c2 << 16);
        int incl = packed;
#pragma unroll
        for (int o = 1; o < 32; o <<= 1) {
            int y = __shfl_up_sync(0xffffffffu, incl, o);
            if (lane >= o) incl += y;
        }
        if (lane == 31) s_wsum[warp] = incl;
        __syncthreads();
        if (warp == 0) {
            int v = (lane < NWARP) ? s_wsum[lane] : 0;
            int e = v;
#pragma unroll
            for (int o = 1; o < NWARP; o <<= 1) {
                int y = __shfl_up_sync(0xffffffffu, e, o);
                if (lane >= o) e += y;
            }
            if (lane < NWARP) s_wsum[lane] = e - v;
            if (lane == NWARP - 1) s_tot = e;
        }
        __syncthreads();
        int gp          = (s_wsum[warp] + (incl - packed)) & 0xffff;
        const int c1tot = s_tot & 0xffff;
        const int c2tot = s_tot >> 16;

        const int n0 = tid * 4;
        const bool pr[4] = {p0, p1, p2, p3};
#pragma unroll
        for (int k = 0; k < 4; k++) {
            int id = n0 + k;
            if (pr[k]) { s_spk[gp] = id; s_spkoff[gp] = id * ROW2; gp++; }
            else       { int np = id - gp; if (np < SIN) s_ns[np] = id; }
        }
        if (tid < 16) s_spkoff[c1tot + tid] = ZOFF2;
        if (p0) v1.x = 0.0f;
        if (p1) v1.y = 0.0f;
        if (p2) v1.z = 0.0f;
        if (p3) v1.w = 0.0f;
        ((float4*)out_st1)[tbIdx * (NN/4) + tid] = v1;
        __syncthreads();

        if (tid < SIN) {
            int id = (tid < c1tot) ? s_spk[tid] : s_ns[tid - c1tot];
            out_ids1[tbIdx * SIN + tid] = (float)id;
        }
        if (tid < 2)
            out_cnt1[tbIdx * 2 + tid] = (float)(tid == 0 ? c1tot : c2tot);

        // layer 2
        float4 acc2 = gather_h2(W2, s_spkoff, (c1tot + 15) & ~15, tid);
        v2.x = d2.x * v2.x + od2.x * acc2.x;
        v2.y = d2.y * v2.y + od2.y * acc2.y;
        v2.z = d2.z * v2.z + od2.z * acc2.z;
        v2.w = d2.w * v2.w + od2.w * acc2.w;
        const bool q0 = v2.x > t2.x, q1 = v2.y > t2.y,
                   q2 = v2.z > t2.z, q3 = v2.w > t2.w;
        c  = (int)q0 + (int)q1 + (int)q2 + (int)q3;
        c2 = (int)(v2.x > h2.x) + (int)(v2.y > h2.y)
           + (int)(v2.z > h2.z) + (int)(v2.w > h2.w);
        packed = c | (c2 << 16);
        incl = packed;
#pragma unroll
        for (int o = 1; o < 32; o <<= 1) {
            int y = __shfl_up_sync(0xffffffffu, incl, o);
            if (lane >= o) incl += y;
        }
        if (lane == 31) s_wsum[warp] = incl;
        __syncthreads();
        if (warp == 0) {
            int v = (lane < NWARP) ? s_wsum[lane] : 0;
            int e = v;
#pragma unroll
            for (int o = 1; o < NWARP; o <<= 1) {
                int y = __shfl_up_sync(0xffffffffu, e, o);
                if (lane >= o) e += y;
            }
            if (lane < NWARP) s_wsum[lane] = e - v;
            if (lane == NWARP - 1) s_tot = e;
        }
        __syncthreads();
        int gq           = (s_wsum[warp] + (incl - packed)) & 0xffff;
        const int c1tot2 = s_tot & 0xffff;
        const int c2tot2 = s_tot >> 16;

        const bool qr[4] = {q0, q1, q2, q3};
#pragma unroll
        for (int k = 0; k < 4; k++) {
            int id = n0 + k;
            if (qr[k]) { if (gq < SIN) s_spk2[gq] = id; gq++; }
            else       { int np = id - gq; if (np < SIN) s_ns2[np] = id; }
        }
        if (q0) v2.x = 0.0f;
        if (q1) v2.y = 0.0f;
        if (q2) v2.z = 0.0f;
        if (q3) v2.w = 0.0f;
        ((float4*)out_st2)[tbIdx * (NN/4) + tid] = v2;
        __syncthreads();

        if (tid < SIN) {
            int id = (tid < c1tot2) ? s_spk2[tid] : s_ns2[tid - c1tot2];
            out_ids2[tbIdx * SIN + tid] = (float)id;
        }
        if (tid < 2)
            out_cnt2[tbIdx * 2 + tid] = (float)(tid == 0 ? c1tot2 : c2tot2);
        __syncthreads();   // s_ids rewrite next step
    }
}

// ---------------------------------------------------------------------------
extern "C" void kernel_launch(void* const* d_in, const int* in_sizes, int n_in,
                              void* d_out, int out_size) {
    const float* W1     = (const float*)d_in[0];
    const float* W2     = (const float*)d_in[1];
    const float* decay1 = (const float*)d_in[2];
    const float* decay2 = (const float*)d_in[3];
    const float* th1    = (const float*)d_in[4];
    const float* th2    = (const float*)d_in[5];
    const float* v1init = (const float*)d_in[6];
    const float* v2init = (const float*)d_in[7];
    const int*   spkids = (const int*)d_in[8];
    const int*   spknum = (const int*)d_in[9];
    float* out = (float*)d_out;

    dim3 tb(32, 8), tg(32, 32, 2);
    transpose_both<<<tg, tb>>>(W1, W2);
    lif_phaseA<<<BATCH * 4, 256>>>(decay1, decay2, th1, th2,
                                   v1init, v2init, spkids, spknum, out);
    lif_fixup<<<BATCH, 256>>>(decay1, decay2, th1, th2,
                              v1init, v2init, spkids, spknum, out);
}